// round 12
// baseline (speedup 1.0000x reference)
#include <cuda_runtime.h>
#include <cuda_bf16.h>
#include <stdint.h>
#include <math.h>

// ---------------------------------------------------------------------------
// MetalsLSTMBlock on GB300, plain compute_103 target (no 'a' features:
// tcgen05/TMEM unavailable -> warp-level mma.sync HMMA + cp.async).
//   rmsnorm(+bf16 hi/lo split) -> fused 4-gate GEMM (+softcap/sigmoid)
//   -> chunked LSTM scan (pass3 emits bf16 hi/lo) -> out GEMM (+residual)
// fp32 GEMMs emulated as 3 bf16 products (hi*hi + hi*lo + lo*hi), fp32 acc;
// rel err ~2^-16, far inside the 1e-3 gate. All operands pre-split in global
// so the GEMM mainloop is pure cp.async + ldmatrix + mma.
// __launch_bounds__(256, 2): 2 CTAs/SM (smem also caps at 2; reg cap 128).
// Gate GEMM folds the 4 weight slabs into grid.x (z fastest) -> L2 A dedup.
// Single-use streams use streaming cache hints.
// Mainloop: per k-half triple (hi*hi -> hi*lo -> lo*hi) with fragment reuse
// (24 unique ldsm4 per chunk instead of 36).
// B=4, S=2048, D=2048, P=2729 (derived from in_sizes at runtime).
// ---------------------------------------------------------------------------

#define BM 128
#define BN 128
#define BKF 32                 // fp32 K elements per chunk
#define PIT 40                 // bf16 pitch of a half tile (32 data + 8 pad)
#define HTB (BM * PIT * 2)     // half-tile bytes = 10240
#define STG (4 * HTB)          // stage = Ahi|Alo|Bhi|Blo = 40960
#define SMEMB (2 * STG)        // double buffered = 81920 (2 CTAs fit)

#define MAX_BS 8192
#define MAX_D  2048
#define MAX_PP 2752            // P padded to multiple of 64 (K dim of GEMM2)
#define MAX_PN 2816            // P padded to multiple of 128 (B rows of GEMM1)
#define MAX_BP 11008           // >= B*P
#define NCHUNK 32              // scan chunks (S % NCHUNK == 0 fast path)

// Scratch (__device__ globals; allocation forbidden). Zero-initialized at
// module load; pad regions are never written -> stay zero and contribute
// nothing (they multiply against zero or are never read).
__device__ __nv_bfloat16 g_xnhi[(size_t)MAX_BS * MAX_D];
__device__ __nv_bfloat16 g_xnlo[(size_t)MAX_BS * MAX_D];
__device__ __nv_bfloat16 g_whi[4ull * MAX_PN * MAX_D];
__device__ __nv_bfloat16 g_wlo[4ull * MAX_PN * MAX_D];
__device__ __nv_bfloat16 g_wohi[(size_t)MAX_D * MAX_PP];
__device__ __nv_bfloat16 g_wolo[(size_t)MAX_D * MAX_PP];
__device__ __nv_bfloat16 g_ohi[(size_t)MAX_BS * MAX_PP];
__device__ __nv_bfloat16 g_olo[(size_t)MAX_BS * MAX_PP];
__device__ float g_gates[4ull * MAX_BS * MAX_PP];
__device__ float g_F[(size_t)NCHUNK * MAX_BP];
__device__ float g_G[(size_t)NCHUNK * MAX_BP];
__device__ float g_hs[(size_t)NCHUNK * MAX_BP];

// ---------------------------------------------------------------------------
// helpers
// ---------------------------------------------------------------------------
__device__ __forceinline__ uint32_t smem_u32(const void* p) {
    uint32_t a;
    asm("{ .reg .u64 t; cvta.to.shared.u64 t, %1; cvt.u32.u64 %0, t; }"
        : "=r"(a) : "l"(p));
    return a;
}
#define CP16(dst, src) \
    asm volatile("cp.async.cg.shared.global [%0], [%1], 16;" \
                 :: "r"(dst), "l"(src))
#define CPCOMMIT() asm volatile("cp.async.commit_group;" ::: "memory")
#define CPWAIT0()  asm volatile("cp.async.wait_group 0;" ::: "memory")

__device__ __forceinline__ void ldsm4(uint32_t* r, uint32_t addr) {
    asm volatile("ldmatrix.sync.aligned.m8n8.x4.shared.b16 {%0,%1,%2,%3}, [%4];"
                 : "=r"(r[0]), "=r"(r[1]), "=r"(r[2]), "=r"(r[3]) : "r"(addr));
}
__device__ __forceinline__ void mma16816(float* c, const uint32_t* a,
                                         uint32_t b0, uint32_t b1) {
    asm volatile(
        "mma.sync.aligned.m16n8k16.row.col.f32.bf16.bf16.f32 "
        "{%0,%1,%2,%3}, {%4,%5,%6,%7}, {%8,%9}, {%0,%1,%2,%3};"
        : "+f"(c[0]), "+f"(c[1]), "+f"(c[2]), "+f"(c[3])
        : "r"(a[0]), "r"(a[1]), "r"(a[2]), "r"(a[3]), "r"(b0), "r"(b1));
}

__device__ __forceinline__ float fast_tanh(float x) {
    float ax = fabsf(x);
    float e = __expf(-2.0f * ax);
    float t = __fdividef(1.0f - e, 1.0f + e);
    return copysignf(t, x);
}
__device__ __forceinline__ float fast_sigmoid(float y) {
    return __fdividef(1.0f, 1.0f + __expf(-y));
}
__device__ __forceinline__ void split1(float v, __nv_bfloat16* hi, __nv_bfloat16* lo) {
    __nv_bfloat16 h = __float2bfloat16(v);
    *hi = h;
    *lo = __float2bfloat16(v - __bfloat162float(h));
}

// ---------------------------------------------------------------------------
// RMS norm + hi/lo split: one block per row of (BS, D)
// ---------------------------------------------------------------------------
__global__ void rms_kernel(const float* __restrict__ x, const float* __restrict__ w,
                           __nv_bfloat16* __restrict__ yhi,
                           __nv_bfloat16* __restrict__ ylo, int D) {
    size_t row = blockIdx.x;
    const float* xr = x + row * (size_t)D;
    __nv_bfloat16* yh = yhi + row * (size_t)D;
    __nv_bfloat16* yl = ylo + row * (size_t)D;

    float ss = 0.f;
    for (int d = threadIdx.x * 4; d < D; d += blockDim.x * 4) {
        float4 v = *(const float4*)&xr[d];
        ss += v.x * v.x + v.y * v.y + v.z * v.z + v.w * v.w;
    }
    #pragma unroll
    for (int o = 16; o > 0; o >>= 1) ss += __shfl_xor_sync(0xFFFFFFFFu, ss, o);
    __shared__ float sred[8];
    int wid = threadIdx.x >> 5, lane = threadIdx.x & 31;
    if (lane == 0) sred[wid] = ss;
    __syncthreads();
    if (wid == 0) {
        float t = (lane < (blockDim.x >> 5)) ? sred[lane] : 0.f;
        #pragma unroll
        for (int o = 4; o > 0; o >>= 1) t += __shfl_xor_sync(0xFFFFFFFFu, t, o);
        if (lane == 0) sred[0] = t;
    }
    __syncthreads();
    float inv = rsqrtf(sred[0] / (float)D + 1e-6f);

    for (int d = threadIdx.x * 4; d < D; d += blockDim.x * 4) {
        float4 v = *(const float4*)&xr[d];
        float4 wv = *(const float4*)&w[d];
        float r0 = wv.x * v.x * inv, r1 = wv.y * v.y * inv;
        float r2 = wv.z * v.z * inv, r3 = wv.w * v.w * inv;
        __nv_bfloat16 h[4], l[4];
        split1(r0, &h[0], &l[0]); split1(r1, &h[1], &l[1]);
        split1(r2, &h[2], &l[2]); split1(r3, &h[3], &l[3]);
        *(uint2*)&yh[d] = *(uint2*)h;
        *(uint2*)&yl[d] = *(uint2*)l;
    }
}

// ---------------------------------------------------------------------------
// Split 4 gate weights (P x D fp32 each) -> padded bf16 hi/lo slabs
// ---------------------------------------------------------------------------
__global__ void wsplit_kernel(const float* __restrict__ w0, const float* __restrict__ w1,
                              const float* __restrict__ w2, const float* __restrict__ w3,
                              __nv_bfloat16* __restrict__ whi,
                              __nv_bfloat16* __restrict__ wlo,
                              int P, int D) {
    size_t i4 = ((size_t)blockIdx.x * blockDim.x + threadIdx.x) * 4;
    size_t per = (size_t)P * D;
    if (i4 >= 4 * per) return;
    int z = (int)(i4 / per);
    size_t rem = i4 - (size_t)z * per;
    const float* W = (z == 0) ? w0 : (z == 1) ? w1 : (z == 2) ? w2 : w3;
    float4 v = *(const float4*)(W + rem);
    __nv_bfloat16 h[4], l[4];
    split1(v.x, &h[0], &l[0]); split1(v.y, &h[1], &l[1]);
    split1(v.z, &h[2], &l[2]); split1(v.w, &h[3], &l[3]);
    size_t dst = (size_t)z * MAX_PN * D + rem;
    *(uint2*)&whi[dst] = *(uint2*)h;
    *(uint2*)&wlo[dst] = *(uint2*)l;
}

// Pad+split Wout (D x P fp32) -> (D x Pp bf16 hi/lo), zero fill
__global__ void wosplit_kernel(const float* __restrict__ w,
                               __nv_bfloat16* __restrict__ whi,
                               __nv_bfloat16* __restrict__ wlo,
                               int D, int P, int Pp) {
    int i = blockIdx.x * blockDim.x + threadIdx.x;
    if (i >= D * Pp) return;
    int d = i / Pp, p = i - d * Pp;
    float v = (p < P) ? w[(size_t)d * P + p] : 0.f;
    __nv_bfloat16 h, l;
    split1(v, &h, &l);
    whi[i] = h;
    wlo[i] = l;
}

// ---------------------------------------------------------------------------
// GEMM: C[m,n] = sum_k A[m,k]*B[n,k]  (NT; pre-split bf16 hi/lo operands)
// CTA 128x128 at (m0, n0), 8 warps of 64x32, K-chunk 32; cp.async double
// buffering. Stage layout: [Ahi | Alo | Bhi | Blo], each 128 x PIT bf16.
// Per k-half schedule with fragment reuse:
//   load Ahi, Bhi -> mma hi*hi; load Blo -> mma hi*lo; load Alo -> mma lo*hi
// (24 unique ldsm4/chunk instead of 36; MMA order per acc element unchanged.)
// ---------------------------------------------------------------------------
__device__ __forceinline__
void gemm_body(int m0, int n0,
               const __nv_bfloat16* __restrict__ Ah, const __nv_bfloat16* __restrict__ Al,
               int lda,
               const __nv_bfloat16* __restrict__ Bh, const __nv_bfloat16* __restrict__ Bl,
               int ldb,
               float* __restrict__ C, int ldc,
               const float* __restrict__ resid,
               int N, int K, int act)
{
    extern __shared__ __align__(16) char smem[];
    const uint32_t sb = smem_u32(smem);
    const int tid = threadIdx.x;
    const int lane = tid & 31;
    const int wid = tid >> 5;
    const int wm = wid >> 2;          // 0..1 -> 64 rows
    const int wn = wid & 3;           // 0..3 -> 32 cols

    const int NK = K / BKF;

    // fill mapping: 2 threads per row; thread covers 16 bf16 (two 16B segs)
    const int frow = tid >> 1;
    const int fk = (tid & 1) << 4;    // 0 or 16
    const __nv_bfloat16* ga = Ah + (size_t)(m0 + frow) * lda + fk;
    const __nv_bfloat16* gal = Al + (size_t)(m0 + frow) * lda + fk;
    const __nv_bfloat16* gb = Bh + (size_t)(n0 + frow) * ldb + fk;
    const __nv_bfloat16* gbl = Bl + (size_t)(n0 + frow) * ldb + fk;
    const uint32_t sd = sb + (uint32_t)(frow * PIT + fk) * 2;

    float acc[4][4][4];
    #pragma unroll
    for (int a = 0; a < 4; a++)
        #pragma unroll
        for (int b = 0; b < 4; b++)
            #pragma unroll
            for (int c = 0; c < 4; c++) acc[a][b][c] = 0.f;

    // prologue: stage 0 <- chunk 0
    {
        CP16(sd,                ga);
        CP16(sd + 16,           ga + 8);
        CP16(sd + HTB,          gal);
        CP16(sd + HTB + 16,     gal + 8);
        CP16(sd + 2 * HTB,      gb);
        CP16(sd + 2 * HTB + 16, gb + 8);
        CP16(sd + 3 * HTB,      gbl);
        CP16(sd + 3 * HTB + 16, gbl + 8);
        CPCOMMIT();
        CPWAIT0();
        __syncthreads();
    }

    const int arow = wm * 64 + (lane & 15);
    const int brow = wn * 32 + (lane & 15);
    const int ksel = (lane >> 4) << 3;

    for (int t = 0; t < NK; t++) {
        if (t + 1 < NK) {
            int ko = (t + 1) * BKF;
            uint32_t ds = sd + ((t + 1) & 1) * STG;
            CP16(ds,                ga + ko);
            CP16(ds + 16,           ga + ko + 8);
            CP16(ds + HTB,          gal + ko);
            CP16(ds + HTB + 16,     gal + ko + 8);
            CP16(ds + 2 * HTB,      gb + ko);
            CP16(ds + 2 * HTB + 16, gb + ko + 8);
            CP16(ds + 3 * HTB,      gbl + ko);
            CP16(ds + 3 * HTB + 16, gbl + ko + 8);
            CPCOMMIT();
        }

        {
            const uint32_t ss = sb + (t & 1) * STG;
            #pragma unroll
            for (int kh = 0; kh < 2; kh++) {       // k-halves 0, 16
                const int kcol = kh * 16 + ksel;
                uint32_t ahf[4][4], alf[4][4], bhf[2][4], blf[2][4];
                // hi*hi: load Ahi + Bhi
                #pragma unroll
                for (int mt = 0; mt < 4; mt++)
                    ldsm4(ahf[mt], ss + 2 * ((arow + mt * 16) * PIT + kcol));
                #pragma unroll
                for (int j = 0; j < 2; j++)
                    ldsm4(bhf[j], ss + 2 * HTB + 2 * ((brow + j * 16) * PIT + kcol));
                #pragma unroll
                for (int mt = 0; mt < 4; mt++)
                    #pragma unroll
                    for (int j = 0; j < 2; j++) {
                        mma16816(acc[mt][2 * j],     ahf[mt], bhf[j][0], bhf[j][2]);
                        mma16816(acc[mt][2 * j + 1], ahf[mt], bhf[j][1], bhf[j][3]);
                    }
                // hi*lo: reuse Ahi, load Blo
                #pragma unroll
                for (int j = 0; j < 2; j++)
                    ldsm4(blf[j], ss + 3 * HTB + 2 * ((brow + j * 16) * PIT + kcol));
                #pragma unroll
                for (int mt = 0; mt < 4; mt++)
                    #pragma unroll
                    for (int j = 0; j < 2; j++) {
                        mma16816(acc[mt][2 * j],     ahf[mt], blf[j][0], blf[j][2]);
                        mma16816(acc[mt][2 * j + 1], ahf[mt], blf[j][1], blf[j][3]);
                    }
                // lo*hi: load Alo, reuse Bhi
                #pragma unroll
                for (int mt = 0; mt < 4; mt++)
                    ldsm4(alf[mt], ss + HTB + 2 * ((arow + mt * 16) * PIT + kcol));
                #pragma unroll
                for (int mt = 0; mt < 4; mt++)
                    #pragma unroll
                    for (int j = 0; j < 2; j++) {
                        mma16816(acc[mt][2 * j],     alf[mt], bhf[j][0], bhf[j][2]);
                        mma16816(acc[mt][2 * j + 1], alf[mt], bhf[j][1], bhf[j][3]);
                    }
            }
        }

        if (t + 1 < NK) {
            CPWAIT0();
            __syncthreads();
        }
    }

    // epilogue: frag c0..c3 = rows (r, r+8) x cols (c, c+1); streaming stores
    #pragma unroll
    for (int mt = 0; mt < 4; mt++) {
        int r0 = m0 + wm * 64 + mt * 16 + (lane >> 2);
        float* crow0 = C + (size_t)r0 * ldc;
        float* crow1 = C + (size_t)(r0 + 8) * ldc;
        const float* rrow0 = resid ? resid + (size_t)r0 * ldc : (const float*)0;
        const float* rrow1 = resid ? resid + (size_t)(r0 + 8) * ldc : (const float*)0;
        #pragma unroll
        for (int nt = 0; nt < 4; nt++) {
            int c = n0 + wn * 32 + nt * 8 + ((lane & 3) << 1);
            float v0 = acc[mt][nt][0], v1 = acc[mt][nt][1];
            float v2 = acc[mt][nt][2], v3 = acc[mt][nt][3];
            if (act) {
                v0 = fast_sigmoid(15.f * fast_tanh(v0 * (1.f / 15.f)));
                v1 = fast_sigmoid(15.f * fast_tanh(v1 * (1.f / 15.f)));
                v2 = fast_sigmoid(15.f * fast_tanh(v2 * (1.f / 15.f)));
                v3 = fast_sigmoid(15.f * fast_tanh(v3 * (1.f / 15.f)));
            }
            if (c + 1 < N) {
                if (rrow0) {
                    float2 ra = __ldcs((const float2*)&rrow0[c]);
                    float2 rb = __ldcs((const float2*)&rrow1[c]);
                    v0 += ra.x; v1 += ra.y;
                    v2 += rb.x; v3 += rb.y;
                }
                __stcs((float2*)&crow0[c], make_float2(v0, v1));
                __stcs((float2*)&crow1[c], make_float2(v2, v3));
            } else if (c < N) {
                if (rrow0) { v0 += __ldcs(&rrow0[c]); v2 += __ldcs(&rrow1[c]); }
                __stcs(&crow0[c], v0);
                __stcs(&crow1[c], v2);
            }
        }
    }
}

// Fused 4-gate GEMM. grid.x = n_tiles*4 with z = blockIdx.x & 3 (z fastest):
// CTAs sharing an (m,n) A tile are wave-co-resident -> A dedup in L2.
// z in {0,1,2}: i/f/o (softcap+sigmoid); z==3: c input (raw).
__global__ __launch_bounds__(256, 2)
void gemm_gates(const __nv_bfloat16* __restrict__ xh, const __nv_bfloat16* __restrict__ xl,
                int lda,
                const __nv_bfloat16* __restrict__ whi, const __nv_bfloat16* __restrict__ wlo,
                size_t wstride,
                float* __restrict__ gates, size_t gsz, int ldc,
                int N, int K)
{
    const int z = blockIdx.x & 3;
    const int n0 = (blockIdx.x >> 2) * BN;
    const int m0 = blockIdx.y * BM;
    gemm_body(m0, n0, xh, xl, lda,
              whi + (size_t)z * wstride, wlo + (size_t)z * wstride, lda,
              gates + (size_t)z * gsz, ldc, (const float*)0, N, K, z != 3);
}

// Output projection GEMM + residual.
__global__ __launch_bounds__(256, 2)
void gemm_out(const __nv_bfloat16* __restrict__ ah, const __nv_bfloat16* __restrict__ al,
              int lda,
              const __nv_bfloat16* __restrict__ bh, const __nv_bfloat16* __restrict__ bl,
              int ldb,
              float* __restrict__ C, int ldc,
              const float* __restrict__ resid, int N, int K)
{
    gemm_body(blockIdx.y * BM, blockIdx.x * BN,
              ah, al, lda, bh, bl, ldb, C, ldc, resid, N, K, 0);
}

// ---------------------------------------------------------------------------
// Chunked LSTM scan. h_s = f_s*h_{s-1} + i_s*tanh(c_s) is affine in h:
// chunk composes to h_end = F*h_start + G (F = prod f, G = recursion from 0).
// All single-use reads use streaming loads (__ldcs).
// ---------------------------------------------------------------------------
__global__ void scan_pass1(const float* __restrict__ gates,
                           float* __restrict__ Fout, float* __restrict__ Gout,
                           int B, int S, int P, int Pp, int CH) {
    int t = blockIdx.x * blockDim.x + threadIdx.x;
    int BP = B * P;
    if (t >= BP * NCHUNK) return;
    int idx = t % BP;
    int c = t / BP;
    int b = idx / P, p = idx - b * P;
    size_t GSZ = (size_t)B * S * Pp;
    size_t base = (size_t)b * S * Pp + p + (size_t)(c * CH) * Pp;
    const float* gi = gates + base;
    const float* gf = gates + GSZ + base;
    const float* gc = gates + 3 * GSZ + base;

    float F = 1.f, G = 0.f;
    #pragma unroll 4
    for (int s = 0; s < CH; s++) {
        size_t off = (size_t)s * Pp;
        float fv = __ldcs(gf + off);
        float iv = __ldcs(gi + off);
        float cv = __ldcs(gc + off);
        G = fv * G + iv * fast_tanh(cv);
        F *= fv;
    }
    Fout[t] = F;
    Gout[t] = G;
}

__global__ void scan_pass2(const float* __restrict__ F, const float* __restrict__ G,
                           const float* __restrict__ h0, float* __restrict__ hs,
                           float* __restrict__ hfin, int BP) {
    int idx = blockIdx.x * blockDim.x + threadIdx.x;
    if (idx >= BP) return;
    float h = h0[idx];
    #pragma unroll
    for (int c = 0; c < NCHUNK; c++) {
        hs[c * BP + idx] = h;
        h = __ldcs(F + c * BP + idx) * h + __ldcs(G + c * BP + idx);
    }
    hfin[idx] = h;
}

__global__ void scan_pass3(const float* __restrict__ gates,
                           const float* __restrict__ hs,
                           __nv_bfloat16* __restrict__ ohi,
                           __nv_bfloat16* __restrict__ olo,
                           int B, int S, int P, int Pp, int CH) {
    int t = blockIdx.x * blockDim.x + threadIdx.x;
    int BP = B * P;
    if (t >= BP * NCHUNK) return;
    int idx = t % BP;
    int c = t / BP;
    int b = idx / P, p = idx - b * P;
    size_t GSZ = (size_t)B * S * Pp;
    size_t base = (size_t)b * S * Pp + p + (size_t)(c * CH) * Pp;
    const float* gi = gates + base;
    const float* gf = gates + GSZ + base;
    const float* go = gates + 2 * GSZ + base;
    const float* gc = gates + 3 * GSZ + base;

    float h = hs[t];
    #pragma unroll 4
    for (int s = 0; s < CH; s++) {
        size_t off = (size_t)s * Pp;
        float fv = __ldcs(gf + off);
        float iv = __ldcs(gi + off);
        float ov = __ldcs(go + off);
        float cv = __ldcs(gc + off);
        h = fv * h + iv * fast_tanh(cv);
        float outv = ov * fast_tanh(h);
        __nv_bfloat16 hh, ll;
        split1(outv, &hh, &ll);
        ohi[base + off] = hh;
        olo[base + off] = ll;
    }
}

// Fallback fully-sequential scan (only if S % NCHUNK != 0).
__global__ void scan_seq(const float* __restrict__ gates,
                         __nv_bfloat16* __restrict__ ohi,
                         __nv_bfloat16* __restrict__ olo,
                         float* __restrict__ hfin, const float* __restrict__ h0,
                         int B, int S, int P, int Pp) {
    int idx = blockIdx.x * blockDim.x + threadIdx.x;
    if (idx >= B * P) return;
    int b = idx / P, p = idx - b * P;
    size_t GSZ = (size_t)B * S * Pp;
    size_t base = (size_t)b * S * Pp + p;
    const float* gi = gates + base;
    const float* gf = gates + GSZ + base;
    const float* go = gates + 2 * GSZ + base;
    const float* gc = gates + 3 * GSZ + base;
    float h = h0[idx];
    #pragma unroll 4
    for (int s = 0; s < S; s++) {
        size_t off = (size_t)s * Pp;
        float iv = __ldcs(gi + off);
        float fv = __ldcs(gf + off);
        float ov = __ldcs(go + off);
        float cv = __ldcs(gc + off);
        h = fv * h + iv * fast_tanh(cv);
        float outv = ov * fast_tanh(h);
        __nv_bfloat16 hh, ll;
        split1(outv, &hh, &ll);
        ohi[base + off] = hh;
        olo[base + off] = ll;
    }
    hfin[idx] = h;
}

// ---------------------------------------------------------------------------
// kernel_launch
// inputs: x, hidden_state, Wi, Wf, Wo, Wc, Wout, ln_weight (all fp32)
// output: [out (B,S,D) | h_final (B,P)]  (h_final only if out_size covers it)
// ---------------------------------------------------------------------------
extern "C" void kernel_launch(void* const* d_in, const int* in_sizes, int n_in,
                              void* d_out, int out_size) {
    (void)n_in;
    const float* x    = (const float*)d_in[0];
    const float* h0   = (const float*)d_in[1];
    const float* Wi   = (const float*)d_in[2];
    const float* Wf   = (const float*)d_in[3];
    const float* Wo   = (const float*)d_in[4];
    const float* Wc   = (const float*)d_in[5];
    const float* Wout = (const float*)d_in[6];
    const float* lnw  = (const float*)d_in[7];

    const int D  = in_sizes[7];              // 2048
    const int BS = in_sizes[0] / D;          // 8192
    const int P  = in_sizes[2] / D;          // 2729
    const int B  = in_sizes[1] / P;          // 4
    const int S  = BS / B;                   // 2048
    const int Pp = (P + 63) & ~63;           // 2752 (mult of 64 -> %32==0)
    const int BP = B * P;

    float* out = (float*)d_out;

    __nv_bfloat16 *xnh, *xnl, *whi, *wlo, *woh, *wol, *ohi, *olo;
    float *gates, *Fbuf, *Gbuf, *hsbuf;
    cudaGetSymbolAddress((void**)&xnh, g_xnhi);
    cudaGetSymbolAddress((void**)&xnl, g_xnlo);
    cudaGetSymbolAddress((void**)&whi, g_whi);
    cudaGetSymbolAddress((void**)&wlo, g_wlo);
    cudaGetSymbolAddress((void**)&woh, g_wohi);
    cudaGetSymbolAddress((void**)&wol, g_wolo);
    cudaGetSymbolAddress((void**)&ohi, g_ohi);
    cudaGetSymbolAddress((void**)&olo, g_olo);
    cudaGetSymbolAddress((void**)&gates, g_gates);
    cudaGetSymbolAddress((void**)&Fbuf, g_F);
    cudaGetSymbolAddress((void**)&Gbuf, g_G);
    cudaGetSymbolAddress((void**)&hsbuf, g_hs);

    // h_final goes into d_out's tail only if out_size actually covers it.
    const size_t BSD = (size_t)BS * D;
    float* hfin = ((size_t)out_size >= BSD + (size_t)BP)
                      ? out + ((size_t)out_size - (size_t)BP)
                      : Fbuf;  // scratch; F fully consumed before hfin written

    // Idempotent attribute sets; unconditional (no static guards allowed).
    cudaFuncSetAttribute(gemm_gates, cudaFuncAttributeMaxDynamicSharedMemorySize,
                         SMEMB);
    cudaFuncSetAttribute(gemm_out, cudaFuncAttributeMaxDynamicSharedMemorySize,
                         SMEMB);

    // 1) RMS norm (+ split)
    rms_kernel<<<BS, 256>>>(x, lnw, xnh, xnl, D);

    // 2) weight splits
    {
        size_t tot4 = 4ull * P * D / 4;
        wsplit_kernel<<<(unsigned)((tot4 + 255) / 256), 256>>>(Wi, Wf, Wo, Wc,
                                                               whi, wlo, P, D);
        int totw = D * Pp;
        wosplit_kernel<<<(totw + 255) / 256, 256>>>(Wout, woh, wol, D, P, Pp);
    }

    // 3) fused gate GEMMs: xn (BS x D) * Wz^T (P x D) -> gates[z] (BS x Pp)
    //    z folded into grid.x (fastest) for L2 A-tile dedup.
    {
        int ntiles = (P + BN - 1) / BN;
        dim3 gg(ntiles * 4, BS / BM, 1);
        size_t GSZ = (size_t)BS * Pp;
        gemm_gates<<<gg, 256, SMEMB>>>(xnh, xnl, D, whi, wlo,
                                       (size_t)MAX_PN * D,
                                       gates, GSZ, Pp, P, D);
    }

    // 4) LSTM scan (chunked 3-pass; pass3 emits bf16 hi/lo)
    if (S % NCHUNK == 0) {
        const int CH = S / NCHUNK;
        int tot = BP * NCHUNK;
        scan_pass1<<<(tot + 255) / 256, 256>>>(gates, Fbuf, Gbuf, B, S, P, Pp, CH);
        scan_pass2<<<(BP + 255) / 256, 256>>>(Fbuf, Gbuf, h0, hsbuf, hfin, BP);
        scan_pass3<<<(tot + 255) / 256, 256>>>(gates, hsbuf, ohi, olo,
                                               B, S, P, Pp, CH);
    } else {
        scan_seq<<<(BP + 255) / 256, 256>>>(gates, ohi, olo, hfin, h0, B, S, P, Pp);
    }

    // 5) output GEMM + residual: oseq (BS x Pp) * Wout^T (D x Pp) -> out (BS x D)
    //    K = Pp exactly (pad cols of oseq and wout are zero)
    dim3 gf((D + BN - 1) / BN, BS / BM);
    gemm_out<<<gf, 256, SMEMB>>>(ohi, olo, Pp, woh, wol, Pp, out, D, x, D, Pp);
}

// round 13
// speedup vs baseline: 1.0374x; 1.0374x over previous
#include <cuda_runtime.h>
#include <cuda_bf16.h>
#include <stdint.h>
#include <math.h>

// ---------------------------------------------------------------------------
// MetalsLSTMBlock on GB300, plain compute_103 target (no 'a' features:
// tcgen05/TMEM unavailable -> warp-level mma.sync HMMA + cp.async).
//   rmsnorm(+bf16 hi/lo split) -> fused 4-gate GEMM (+softcap/sigmoid)
//   -> chunked LSTM scan (pass3 emits bf16 hi/lo) -> out GEMM (+residual)
// fp32 GEMMs emulated as 3 bf16 products (hi*hi + hi*lo + lo*hi), fp32 acc;
// measured rel_err 7.7e-6 (gate 1e-3). Operands pre-split in global; GEMM
// mainloop is pure cp.async + ldmatrix + mma.
// R13 change: 4-stage cp.async pipeline (BKF=16, wait_group 2) to kill the
// per-chunk load-wait convoy seen in R12 ncu (tensor 52%, issue 25%).
// __launch_bounds__(256, 2): 2 CTAs/SM. Gate GEMM z-folded into grid.x for
// L2 A dedup. Single-use streams use streaming cache hints.
// B=4, S=2048, D=2048, P=2729 (derived from in_sizes at runtime).
// ---------------------------------------------------------------------------

#define BM 128
#define BN 128
#define BKF 16                 // fp32 K elements per chunk (one k16 MMA step)
#define PIT 24                 // bf16 pitch of a half tile (16 data + 8 pad)
#define HTB (BM * PIT * 2)     // half-tile bytes = 6144
#define STG (4 * HTB)          // stage = Ahi|Alo|Bhi|Blo = 24576
#define NSTAGE 4
#define SMEMB (NSTAGE * STG)   // 98304 (2 CTAs fit in 228KB)

#define MAX_BS 8192
#define MAX_D  2048
#define MAX_PP 2752            // P padded to multiple of 64 (K dim of GEMM2)
#define MAX_PN 2816            // P padded to multiple of 128 (B rows of GEMM1)
#define MAX_BP 11008           // >= B*P
#define NCHUNK 32              // scan chunks (S % NCHUNK == 0 fast path)

// Scratch (__device__ globals; allocation forbidden). Zero-initialized at
// module load; pad regions are never written -> stay zero.
__device__ __nv_bfloat16 g_xnhi[(size_t)MAX_BS * MAX_D];
__device__ __nv_bfloat16 g_xnlo[(size_t)MAX_BS * MAX_D];
__device__ __nv_bfloat16 g_whi[4ull * MAX_PN * MAX_D];
__device__ __nv_bfloat16 g_wlo[4ull * MAX_PN * MAX_D];
__device__ __nv_bfloat16 g_wohi[(size_t)MAX_D * MAX_PP];
__device__ __nv_bfloat16 g_wolo[(size_t)MAX_D * MAX_PP];
__device__ __nv_bfloat16 g_ohi[(size_t)MAX_BS * MAX_PP];
__device__ __nv_bfloat16 g_olo[(size_t)MAX_BS * MAX_PP];
__device__ float g_gates[4ull * MAX_BS * MAX_PP];
__device__ float g_F[(size_t)NCHUNK * MAX_BP];
__device__ float g_G[(size_t)NCHUNK * MAX_BP];
__device__ float g_hs[(size_t)NCHUNK * MAX_BP];

// ---------------------------------------------------------------------------
// helpers
// ---------------------------------------------------------------------------
__device__ __forceinline__ uint32_t smem_u32(const void* p) {
    uint32_t a;
    asm("{ .reg .u64 t; cvta.to.shared.u64 t, %1; cvt.u32.u64 %0, t; }"
        : "=r"(a) : "l"(p));
    return a;
}
#define CP16(dst, src) \
    asm volatile("cp.async.cg.shared.global [%0], [%1], 16;" \
                 :: "r"(dst), "l"(src))
#define CPCOMMIT() asm volatile("cp.async.commit_group;" ::: "memory")
#define CPWAIT(n)  asm volatile("cp.async.wait_group %0;" :: "n"(n) : "memory")

__device__ __forceinline__ void ldsm4(uint32_t* r, uint32_t addr) {
    asm volatile("ldmatrix.sync.aligned.m8n8.x4.shared.b16 {%0,%1,%2,%3}, [%4];"
                 : "=r"(r[0]), "=r"(r[1]), "=r"(r[2]), "=r"(r[3]) : "r"(addr));
}
__device__ __forceinline__ void mma16816(float* c, const uint32_t* a,
                                         uint32_t b0, uint32_t b1) {
    asm volatile(
        "mma.sync.aligned.m16n8k16.row.col.f32.bf16.bf16.f32 "
        "{%0,%1,%2,%3}, {%4,%5,%6,%7}, {%8,%9}, {%0,%1,%2,%3};"
        : "+f"(c[0]), "+f"(c[1]), "+f"(c[2]), "+f"(c[3])
        : "r"(a[0]), "r"(a[1]), "r"(a[2]), "r"(a[3]), "r"(b0), "r"(b1));
}

__device__ __forceinline__ float fast_tanh(float x) {
    float ax = fabsf(x);
    float e = __expf(-2.0f * ax);
    float t = __fdividef(1.0f - e, 1.0f + e);
    return copysignf(t, x);
}
__device__ __forceinline__ float fast_sigmoid(float y) {
    return __fdividef(1.0f, 1.0f + __expf(-y));
}
__device__ __forceinline__ void split1(float v, __nv_bfloat16* hi, __nv_bfloat16* lo) {
    __nv_bfloat16 h = __float2bfloat16(v);
    *hi = h;
    *lo = __float2bfloat16(v - __bfloat162float(h));
}

// ---------------------------------------------------------------------------
// RMS norm + hi/lo split: one block per row of (BS, D)
// ---------------------------------------------------------------------------
__global__ void rms_kernel(const float* __restrict__ x, const float* __restrict__ w,
                           __nv_bfloat16* __restrict__ yhi,
                           __nv_bfloat16* __restrict__ ylo, int D) {
    size_t row = blockIdx.x;
    const float* xr = x + row * (size_t)D;
    __nv_bfloat16* yh = yhi + row * (size_t)D;
    __nv_bfloat16* yl = ylo + row * (size_t)D;

    float ss = 0.f;
    for (int d = threadIdx.x * 4; d < D; d += blockDim.x * 4) {
        float4 v = *(const float4*)&xr[d];
        ss += v.x * v.x + v.y * v.y + v.z * v.z + v.w * v.w;
    }
    #pragma unroll
    for (int o = 16; o > 0; o >>= 1) ss += __shfl_xor_sync(0xFFFFFFFFu, ss, o);
    __shared__ float sred[8];
    int wid = threadIdx.x >> 5, lane = threadIdx.x & 31;
    if (lane == 0) sred[wid] = ss;
    __syncthreads();
    if (wid == 0) {
        float t = (lane < (blockDim.x >> 5)) ? sred[lane] : 0.f;
        #pragma unroll
        for (int o = 4; o > 0; o >>= 1) t += __shfl_xor_sync(0xFFFFFFFFu, t, o);
        if (lane == 0) sred[0] = t;
    }
    __syncthreads();
    float inv = rsqrtf(sred[0] / (float)D + 1e-6f);

    for (int d = threadIdx.x * 4; d < D; d += blockDim.x * 4) {
        float4 v = *(const float4*)&xr[d];
        float4 wv = *(const float4*)&w[d];
        float r0 = wv.x * v.x * inv, r1 = wv.y * v.y * inv;
        float r2 = wv.z * v.z * inv, r3 = wv.w * v.w * inv;
        __nv_bfloat16 h[4], l[4];
        split1(r0, &h[0], &l[0]); split1(r1, &h[1], &l[1]);
        split1(r2, &h[2], &l[2]); split1(r3, &h[3], &l[3]);
        *(uint2*)&yh[d] = *(uint2*)h;
        *(uint2*)&yl[d] = *(uint2*)l;
    }
}

// ---------------------------------------------------------------------------
// Split 4 gate weights (P x D fp32 each) -> padded bf16 hi/lo slabs
// ---------------------------------------------------------------------------
__global__ void wsplit_kernel(const float* __restrict__ w0, const float* __restrict__ w1,
                              const float* __restrict__ w2, const float* __restrict__ w3,
                              __nv_bfloat16* __restrict__ whi,
                              __nv_bfloat16* __restrict__ wlo,
                              int P, int D) {
    size_t i4 = ((size_t)blockIdx.x * blockDim.x + threadIdx.x) * 4;
    size_t per = (size_t)P * D;
    if (i4 >= 4 * per) return;
    int z = (int)(i4 / per);
    size_t rem = i4 - (size_t)z * per;
    const float* W = (z == 0) ? w0 : (z == 1) ? w1 : (z == 2) ? w2 : w3;
    float4 v = *(const float4*)(W + rem);
    __nv_bfloat16 h[4], l[4];
    split1(v.x, &h[0], &l[0]); split1(v.y, &h[1], &l[1]);
    split1(v.z, &h[2], &l[2]); split1(v.w, &h[3], &l[3]);
    size_t dst = (size_t)z * MAX_PN * D + rem;
    *(uint2*)&whi[dst] = *(uint2*)h;
    *(uint2*)&wlo[dst] = *(uint2*)l;
}

// Pad+split Wout (D x P fp32) -> (D x Pp bf16 hi/lo), zero fill
__global__ void wosplit_kernel(const float* __restrict__ w,
                               __nv_bfloat16* __restrict__ whi,
                               __nv_bfloat16* __restrict__ wlo,
                               int D, int P, int Pp) {
    int i = blockIdx.x * blockDim.x + threadIdx.x;
    if (i >= D * Pp) return;
    int d = i / Pp, p = i - d * Pp;
    float v = (p < P) ? w[(size_t)d * P + p] : 0.f;
    __nv_bfloat16 h, l;
    split1(v, &h, &l);
    whi[i] = h;
    wlo[i] = l;
}

// ---------------------------------------------------------------------------
// GEMM: C[m,n] = sum_k A[m,k]*B[n,k]  (NT; pre-split bf16 hi/lo operands)
// CTA 128x128 at (m0, n0), 8 warps of 64x32, K-chunk 16, 4-stage cp.async
// pipeline (loads run 3 chunks ahead; wait_group 2 in steady state).
// Stage layout: [Ahi | Alo | Bhi | Blo], each 128 x PIT bf16.
// Per chunk: one k16 step x 3 products with fragment reuse (12 ldsm, 48 mma).
// ---------------------------------------------------------------------------
__device__ __forceinline__
void gemm_body(int m0, int n0,
               const __nv_bfloat16* __restrict__ Ah, const __nv_bfloat16* __restrict__ Al,
               int lda,
               const __nv_bfloat16* __restrict__ Bh, const __nv_bfloat16* __restrict__ Bl,
               int ldb,
               float* __restrict__ C, int ldc,
               const float* __restrict__ resid,
               int N, int K, int act)
{
    extern __shared__ __align__(16) char smem[];
    const uint32_t sb = smem_u32(smem);
    const int tid = threadIdx.x;
    const int lane = tid & 31;
    const int wid = tid >> 5;
    const int wm = wid >> 2;          // 0..1 -> 64 rows
    const int wn = wid & 3;           // 0..3 -> 32 cols

    const int NK = K / BKF;

    // fill mapping: 2 threads per row; each covers 8 bf16 (one 16B segment)
    const int frow = tid >> 1;
    const int fseg = (tid & 1) << 3;  // 0 or 8 bf16
    const __nv_bfloat16* ga  = Ah + (size_t)(m0 + frow) * lda + fseg;
    const __nv_bfloat16* gal = Al + (size_t)(m0 + frow) * lda + fseg;
    const __nv_bfloat16* gb  = Bh + (size_t)(n0 + frow) * ldb + fseg;
    const __nv_bfloat16* gbl = Bl + (size_t)(n0 + frow) * ldb + fseg;
    const uint32_t sd = sb + (uint32_t)(frow * PIT + fseg) * 2;

    float acc[4][4][4];
    #pragma unroll
    for (int a = 0; a < 4; a++)
        #pragma unroll
        for (int b = 0; b < 4; b++)
            #pragma unroll
            for (int c = 0; c < 4; c++) acc[a][b][c] = 0.f;

    // prologue: stages 0..NSTAGE-2 <- chunks 0..NSTAGE-2
    #pragma unroll
    for (int s = 0; s < NSTAGE - 1; s++) {
        if (s < NK) {
            int ko = s * BKF;
            uint32_t ds = sd + s * STG;
            CP16(ds,           ga + ko);
            CP16(ds + HTB,     gal + ko);
            CP16(ds + 2 * HTB, gb + ko);
            CP16(ds + 3 * HTB, gbl + ko);
        }
        CPCOMMIT();
    }

    const int arow = wm * 64 + (lane & 15);
    const int brow = wn * 32 + (lane & 15);
    const int ksel = (lane >> 4) << 3;

    for (int t = 0; t < NK; t++) {
        // steady state: group for chunk t is 3 groups old -> done; wait is a
        // no-op unless the memory system fell behind by >2 chunks.
        CPWAIT(NSTAGE - 2);
        __syncthreads();   // also separates compute(t-1) from the overwrite below

        {
            const uint32_t ss = sb + (uint32_t)(t % NSTAGE) * STG;
            uint32_t ahf[4][4], alf[4][4], bhf[2][4], blf[2][4];
            // hi*hi: load Ahi + Bhi
            #pragma unroll
            for (int mt = 0; mt < 4; mt++)
                ldsm4(ahf[mt], ss + 2 * ((arow + mt * 16) * PIT + ksel));
            #pragma unroll
            for (int j = 0; j < 2; j++)
                ldsm4(bhf[j], ss + 2 * HTB + 2 * ((brow + j * 16) * PIT + ksel));
            #pragma unroll
            for (int mt = 0; mt < 4; mt++)
                #pragma unroll
                for (int j = 0; j < 2; j++) {
                    mma16816(acc[mt][2 * j],     ahf[mt], bhf[j][0], bhf[j][2]);
                    mma16816(acc[mt][2 * j + 1], ahf[mt], bhf[j][1], bhf[j][3]);
                }
            // hi*lo: reuse Ahi, load Blo
            #pragma unroll
            for (int j = 0; j < 2; j++)
                ldsm4(blf[j], ss + 3 * HTB + 2 * ((brow + j * 16) * PIT + ksel));
            #pragma unroll
            for (int mt = 0; mt < 4; mt++)
                #pragma unroll
                for (int j = 0; j < 2; j++) {
                    mma16816(acc[mt][2 * j],     ahf[mt], blf[j][0], blf[j][2]);
                    mma16816(acc[mt][2 * j + 1], ahf[mt], blf[j][1], blf[j][3]);
                }
            // lo*hi: load Alo, reuse Bhi
            #pragma unroll
            for (int mt = 0; mt < 4; mt++)
                ldsm4(alf[mt], ss + HTB + 2 * ((arow + mt * 16) * PIT + ksel));
            #pragma unroll
            for (int mt = 0; mt < 4; mt++)
                #pragma unroll
                for (int j = 0; j < 2; j++) {
                    mma16816(acc[mt][2 * j],     alf[mt], bhf[j][0], bhf[j][2]);
                    mma16816(acc[mt][2 * j + 1], alf[mt], bhf[j][1], bhf[j][3]);
                }
        }

        // issue load for chunk t+NSTAGE-1 (overwrites stage (t-1)%NSTAGE,
        // whose readers finished before this iteration's barrier).
        if (t + NSTAGE - 1 < NK) {
            int ko = (t + NSTAGE - 1) * BKF;
            uint32_t ds = sd + (uint32_t)((t + NSTAGE - 1) % NSTAGE) * STG;
            CP16(ds,           ga + ko);
            CP16(ds + HTB,     gal + ko);
            CP16(ds + 2 * HTB, gb + ko);
            CP16(ds + 3 * HTB, gbl + ko);
        }
        CPCOMMIT();   // empty group in tail keeps wait_group accounting aligned
    }

    // epilogue: frag c0..c3 = rows (r, r+8) x cols (c, c+1); streaming stores
    #pragma unroll
    for (int mt = 0; mt < 4; mt++) {
        int r0 = m0 + wm * 64 + mt * 16 + (lane >> 2);
        float* crow0 = C + (size_t)r0 * ldc;
        float* crow1 = C + (size_t)(r0 + 8) * ldc;
        const float* rrow0 = resid ? resid + (size_t)r0 * ldc : (const float*)0;
        const float* rrow1 = resid ? resid + (size_t)(r0 + 8) * ldc : (const float*)0;
        #pragma unroll
        for (int nt = 0; nt < 4; nt++) {
            int c = n0 + wn * 32 + nt * 8 + ((lane & 3) << 1);
            float v0 = acc[mt][nt][0], v1 = acc[mt][nt][1];
            float v2 = acc[mt][nt][2], v3 = acc[mt][nt][3];
            if (act) {
                v0 = fast_sigmoid(15.f * fast_tanh(v0 * (1.f / 15.f)));
                v1 = fast_sigmoid(15.f * fast_tanh(v1 * (1.f / 15.f)));
                v2 = fast_sigmoid(15.f * fast_tanh(v2 * (1.f / 15.f)));
                v3 = fast_sigmoid(15.f * fast_tanh(v3 * (1.f / 15.f)));
            }
            if (c + 1 < N) {
                if (rrow0) {
                    float2 ra = __ldcs((const float2*)&rrow0[c]);
                    float2 rb = __ldcs((const float2*)&rrow1[c]);
                    v0 += ra.x; v1 += ra.y;
                    v2 += rb.x; v3 += rb.y;
                }
                __stcs((float2*)&crow0[c], make_float2(v0, v1));
                __stcs((float2*)&crow1[c], make_float2(v2, v3));
            } else if (c < N) {
                if (rrow0) { v0 += __ldcs(&rrow0[c]); v2 += __ldcs(&rrow1[c]); }
                __stcs(&crow0[c], v0);
                __stcs(&crow1[c], v2);
            }
        }
    }
}

// Fused 4-gate GEMM. grid.x = n_tiles*4 with z = blockIdx.x & 3 (z fastest):
// CTAs sharing an (m,n) A tile are wave-co-resident -> A dedup in L2.
// z in {0,1,2}: i/f/o (softcap+sigmoid); z==3: c input (raw).
__global__ __launch_bounds__(256, 2)
void gemm_gates(const __nv_bfloat16* __restrict__ xh, const __nv_bfloat16* __restrict__ xl,
                int lda,
                const __nv_bfloat16* __restrict__ whi, const __nv_bfloat16* __restrict__ wlo,
                size_t wstride,
                float* __restrict__ gates, size_t gsz, int ldc,
                int N, int K)
{
    const int z = blockIdx.x & 3;
    const int n0 = (blockIdx.x >> 2) * BN;
    const int m0 = blockIdx.y * BM;
    gemm_body(m0, n0, xh, xl, lda,
              whi + (size_t)z * wstride, wlo + (size_t)z * wstride, lda,
              gates + (size_t)z * gsz, ldc, (const float*)0, N, K, z != 3);
}

// Output projection GEMM + residual.
__global__ __launch_bounds__(256, 2)
void gemm_out(const __nv_bfloat16* __restrict__ ah, const __nv_bfloat16* __restrict__ al,
              int lda,
              const __nv_bfloat16* __restrict__ bh, const __nv_bfloat16* __restrict__ bl,
              int ldb,
              float* __restrict__ C, int ldc,
              const float* __restrict__ resid, int N, int K)
{
    gemm_body(blockIdx.y * BM, blockIdx.x * BN,
              ah, al, lda, bh, bl, ldb, C, ldc, resid, N, K, 0);
}

// ---------------------------------------------------------------------------
// Chunked LSTM scan. h_s = f_s*h_{s-1} + i_s*tanh(c_s) is affine in h:
// chunk composes to h_end = F*h_start + G (F = prod f, G = recursion from 0).
// All single-use reads use streaming loads (__ldcs).
// ---------------------------------------------------------------------------
__global__ void scan_pass1(const float* __restrict__ gates,
                           float* __restrict__ Fout, float* __restrict__ Gout,
                           int B, int S, int P, int Pp, int CH) {
    int t = blockIdx.x * blockDim.x + threadIdx.x;
    int BP = B * P;
    if (t >= BP * NCHUNK) return;
    int idx = t % BP;
    int c = t / BP;
    int b = idx / P, p = idx - b * P;
    size_t GSZ = (size_t)B * S * Pp;
    size_t base = (size_t)b * S * Pp + p + (size_t)(c * CH) * Pp;
    const float* gi = gates + base;
    const float* gf = gates + GSZ + base;
    const float* gc = gates + 3 * GSZ + base;

    float F = 1.f, G = 0.f;
    #pragma unroll 4
    for (int s = 0; s < CH; s++) {
        size_t off = (size_t)s * Pp;
        float fv = __ldcs(gf + off);
        float iv = __ldcs(gi + off);
        float cv = __ldcs(gc + off);
        G = fv * G + iv * fast_tanh(cv);
        F *= fv;
    }
    Fout[t] = F;
    Gout[t] = G;
}

__global__ void scan_pass2(const float* __restrict__ F, const float* __restrict__ G,
                           const float* __restrict__ h0, float* __restrict__ hs,
                           float* __restrict__ hfin, int BP) {
    int idx = blockIdx.x * blockDim.x + threadIdx.x;
    if (idx >= BP) return;
    float h = h0[idx];
    #pragma unroll
    for (int c = 0; c < NCHUNK; c++) {
        hs[c * BP + idx] = h;
        h = __ldcs(F + c * BP + idx) * h + __ldcs(G + c * BP + idx);
    }
    hfin[idx] = h;
}

__global__ void scan_pass3(const float* __restrict__ gates,
                           const float* __restrict__ hs,
                           __nv_bfloat16* __restrict__ ohi,
                           __nv_bfloat16* __restrict__ olo,
                           int B, int S, int P, int Pp, int CH) {
    int t = blockIdx.x * blockDim.x + threadIdx.x;
    int BP = B * P;
    if (t >= BP * NCHUNK) return;
    int idx = t % BP;
    int c = t / BP;
    int b = idx / P, p = idx - b * P;
    size_t GSZ = (size_t)B * S * Pp;
    size_t base = (size_t)b * S * Pp + p + (size_t)(c * CH) * Pp;
    const float* gi = gates + base;
    const float* gf = gates + GSZ + base;
    const float* go = gates + 2 * GSZ + base;
    const float* gc = gates + 3 * GSZ + base;

    float h = hs[t];
    #pragma unroll 4
    for (int s = 0; s < CH; s++) {
        size_t off = (size_t)s * Pp;
        float fv = __ldcs(gf + off);
        float iv = __ldcs(gi + off);
        float ov = __ldcs(go + off);
        float cv = __ldcs(gc + off);
        h = fv * h + iv * fast_tanh(cv);
        float outv = ov * fast_tanh(h);
        __nv_bfloat16 hh, ll;
        split1(outv, &hh, &ll);
        ohi[base + off] = hh;
        olo[base + off] = ll;
    }
}

// Fallback fully-sequential scan (only if S % NCHUNK != 0).
__global__ void scan_seq(const float* __restrict__ gates,
                         __nv_bfloat16* __restrict__ ohi,
                         __nv_bfloat16* __restrict__ olo,
                         float* __restrict__ hfin, const float* __restrict__ h0,
                         int B, int S, int P, int Pp) {
    int idx = blockIdx.x * blockDim.x + threadIdx.x;
    if (idx >= B * P) return;
    int b = idx / P, p = idx - b * P;
    size_t GSZ = (size_t)B * S * Pp;
    size_t base = (size_t)b * S * Pp + p;
    const float* gi = gates + base;
    const float* gf = gates + GSZ + base;
    const float* go = gates + 2 * GSZ + base;
    const float* gc = gates + 3 * GSZ + base;
    float h = h0[idx];
    #pragma unroll 4
    for (int s = 0; s < S; s++) {
        size_t off = (size_t)s * Pp;
        float iv = __ldcs(gi + off);
        float fv = __ldcs(gf + off);
        float ov = __ldcs(go + off);
        float cv = __ldcs(gc + off);
        h = fv * h + iv * fast_tanh(cv);
        float outv = ov * fast_tanh(h);
        __nv_bfloat16 hh, ll;
        split1(outv, &hh, &ll);
        ohi[base + off] = hh;
        olo[base + off] = ll;
    }
    hfin[idx] = h;
}

// ---------------------------------------------------------------------------
// kernel_launch
// inputs: x, hidden_state, Wi, Wf, Wo, Wc, Wout, ln_weight (all fp32)
// output: [out (B,S,D) | h_final (B,P)]  (h_final only if out_size covers it)
// ---------------------------------------------------------------------------
extern "C" void kernel_launch(void* const* d_in, const int* in_sizes, int n_in,
                              void* d_out, int out_size) {
    (void)n_in;
    const float* x    = (const float*)d_in[0];
    const float* h0   = (const float*)d_in[1];
    const float* Wi   = (const float*)d_in[2];
    const float* Wf   = (const float*)d_in[3];
    const float* Wo   = (const float*)d_in[4];
    const float* Wc   = (const float*)d_in[5];
    const float* Wout = (const float*)d_in[6];
    const float* lnw  = (const float*)d_in[7];

    const int D  = in_sizes[7];              // 2048
    const int BS = in_sizes[0] / D;          // 8192
    const int P  = in_sizes[2] / D;          // 2729
    const int B  = in_sizes[1] / P;          // 4
    const int S  = BS / B;                   // 2048
    const int Pp = (P + 63) & ~63;           // 2752 (mult of 64 -> %16==0)
    const int BP = B * P;

    float* out = (float*)d_out;

    __nv_bfloat16 *xnh, *xnl, *whi, *wlo, *woh, *wol, *ohi, *olo;
    float *gates, *Fbuf, *Gbuf, *hsbuf;
    cudaGetSymbolAddress((void**)&xnh, g_xnhi);
    cudaGetSymbolAddress((void**)&xnl, g_xnlo);
    cudaGetSymbolAddress((void**)&whi, g_whi);
    cudaGetSymbolAddress((void**)&wlo, g_wlo);
    cudaGetSymbolAddress((void**)&woh, g_wohi);
    cudaGetSymbolAddress((void**)&wol, g_wolo);
    cudaGetSymbolAddress((void**)&ohi, g_ohi);
    cudaGetSymbolAddress((void**)&olo, g_olo);
    cudaGetSymbolAddress((void**)&gates, g_gates);
    cudaGetSymbolAddress((void**)&Fbuf, g_F);
    cudaGetSymbolAddress((void**)&Gbuf, g_G);
    cudaGetSymbolAddress((void**)&hsbuf, g_hs);

    // h_final goes into d_out's tail only if out_size actually covers it.
    const size_t BSD = (size_t)BS * D;
    float* hfin = ((size_t)out_size >= BSD + (size_t)BP)
                      ? out + ((size_t)out_size - (size_t)BP)
                      : Fbuf;  // scratch; F fully consumed before hfin written

    // Idempotent attribute sets; unconditional (no static guards allowed).
    cudaFuncSetAttribute(gemm_gates, cudaFuncAttributeMaxDynamicSharedMemorySize,
                         SMEMB);
    cudaFuncSetAttribute(gemm_out, cudaFuncAttributeMaxDynamicSharedMemorySize,
                         SMEMB);

    // 1) RMS norm (+ split)
    rms_kernel<<<BS, 256>>>(x, lnw, xnh, xnl, D);

    // 2) weight splits
    {
        size_t tot4 = 4ull * P * D / 4;
        wsplit_kernel<<<(unsigned)((tot4 + 255) / 256), 256>>>(Wi, Wf, Wo, Wc,
                                                               whi, wlo, P, D);
        int totw = D * Pp;
        wosplit_kernel<<<(totw + 255) / 256, 256>>>(Wout, woh, wol, D, P, Pp);
    }

    // 3) fused gate GEMMs: xn (BS x D) * Wz^T (P x D) -> gates[z] (BS x Pp)
    //    z folded into grid.x (fastest) for L2 A-tile dedup.
    {
        int ntiles = (P + BN - 1) / BN;
        dim3 gg(ntiles * 4, BS / BM, 1);
        size_t GSZ = (size_t)BS * Pp;
        gemm_gates<<<gg, 256, SMEMB>>>(xnh, xnl, D, whi, wlo,
                                       (size_t)MAX_PN * D,
                                       gates, GSZ, Pp, P, D);
    }

    // 4) LSTM scan (chunked 3-pass; pass3 emits bf16 hi/lo)
    if (S % NCHUNK == 0) {
        const int CH = S / NCHUNK;
        int tot = BP * NCHUNK;
        scan_pass1<<<(tot + 255) / 256, 256>>>(gates, Fbuf, Gbuf, B, S, P, Pp, CH);
        scan_pass2<<<(BP + 255) / 256, 256>>>(Fbuf, Gbuf, h0, hsbuf, hfin, BP);
        scan_pass3<<<(tot + 255) / 256, 256>>>(gates, hsbuf, ohi, olo,
                                               B, S, P, Pp, CH);
    } else {
        scan_seq<<<(BP + 255) / 256, 256>>>(gates, ohi, olo, hfin, h0, B, S, P, Pp);
    }

    // 5) output GEMM + residual: oseq (BS x Pp) * Wout^T (D x Pp) -> out (BS x D)
    //    K = Pp exactly (pad cols of oseq and wout are zero)
    dim3 gf((D + BN - 1) / BN, BS / BM);
    gemm_out<<<gf, 256, SMEMB>>>(ohi, olo, Pp, woh, wol, Pp, out, D, x, D, Pp);
}

// round 17
// speedup vs baseline: 1.2029x; 1.1595x over previous
#include <cuda_runtime.h>
#include <cuda_bf16.h>
#include <stdint.h>
#include <math.h>

// ---------------------------------------------------------------------------
// MetalsLSTMBlock on GB300, plain compute_103 target (no 'a' features).
//   rmsnorm(+bf16 hi/lo split) -> fused 4-gate GEMM (+softcap/sigmoid)
//   -> chunked LSTM scan -> out GEMM (+residual)
// fp32 GEMMs emulated as 3 bf16 products (hi*hi + hi*lo + lo*hi), fp32 acc;
// measured rel_err 7.7e-6. Operands pre-split in global.
// R17 == R14/R15/R16 (unbenched due to GPU outages): register-level fragment
// prefetch one chunk ahead kills the per-chunk ldsm->mma scoreboard bubble
// that pinned tensor at ~54% in R12/R13. CPWAIT(1)+bar at loop bottom
// guarantees chunk t+2 is CTA-visible at the top of iter t+1.
// ---------------------------------------------------------------------------

#define BM 128
#define BN 128
#define BKF 16                 // fp32 K elements per chunk (one k16 MMA step)
#define PIT 24                 // bf16 pitch of a half tile (16 data + 8 pad)
#define HTB (BM * PIT * 2)     // half-tile bytes = 6144
#define STG (4 * HTB)          // stage = Ahi|Alo|Bhi|Blo = 24576
#define NSTAGE 4
#define SMEMB (NSTAGE * STG)   // 98304 (2 CTAs fit in 228KB)

#define MAX_BS 8192
#define MAX_D  2048
#define MAX_PP 2752            // P padded to multiple of 64 (K dim of GEMM2)
#define MAX_PN 2816            // P padded to multiple of 128 (B rows of GEMM1)
#define MAX_BP 11008           // >= B*P
#define NCHUNK 32              // scan chunks (S % NCHUNK == 0 fast path)

// Scratch (__device__ globals; allocation forbidden). Zero-initialized;
// pad regions never written -> stay zero.
__device__ __nv_bfloat16 g_xnhi[(size_t)MAX_BS * MAX_D];
__device__ __nv_bfloat16 g_xnlo[(size_t)MAX_BS * MAX_D];
__device__ __nv_bfloat16 g_whi[4ull * MAX_PN * MAX_D];
__device__ __nv_bfloat16 g_wlo[4ull * MAX_PN * MAX_D];
__device__ __nv_bfloat16 g_wohi[(size_t)MAX_D * MAX_PP];
__device__ __nv_bfloat16 g_wolo[(size_t)MAX_D * MAX_PP];
__device__ __nv_bfloat16 g_ohi[(size_t)MAX_BS * MAX_PP];
__device__ __nv_bfloat16 g_olo[(size_t)MAX_BS * MAX_PP];
__device__ float g_gates[4ull * MAX_BS * MAX_PP];
__device__ float g_F[(size_t)NCHUNK * MAX_BP];
__device__ float g_G[(size_t)NCHUNK * MAX_BP];
__device__ float g_hs[(size_t)NCHUNK * MAX_BP];

// ---------------------------------------------------------------------------
// helpers
// ---------------------------------------------------------------------------
__device__ __forceinline__ uint32_t smem_u32(const void* p) {
    uint32_t a;
    asm("{ .reg .u64 t; cvta.to.shared.u64 t, %1; cvt.u32.u64 %0, t; }"
        : "=r"(a) : "l"(p));
    return a;
}
#define CP16(dst, src) \
    asm volatile("cp.async.cg.shared.global [%0], [%1], 16;" \
                 :: "r"(dst), "l"(src))
#define CPCOMMIT() asm volatile("cp.async.commit_group;" ::: "memory")
#define CPWAIT(n)  asm volatile("cp.async.wait_group %0;" :: "n"(n) : "memory")

__device__ __forceinline__ void ldsm4(uint32_t* r, uint32_t addr) {
    asm volatile("ldmatrix.sync.aligned.m8n8.x4.shared.b16 {%0,%1,%2,%3}, [%4];"
                 : "=r"(r[0]), "=r"(r[1]), "=r"(r[2]), "=r"(r[3]) : "r"(addr));
}
__device__ __forceinline__ void mma16816(float* c, const uint32_t* a,
                                         uint32_t b0, uint32_t b1) {
    asm volatile(
        "mma.sync.aligned.m16n8k16.row.col.f32.bf16.bf16.f32 "
        "{%0,%1,%2,%3}, {%4,%5,%6,%7}, {%8,%9}, {%0,%1,%2,%3};"
        : "+f"(c[0]), "+f"(c[1]), "+f"(c[2]), "+f"(c[3])
        : "r"(a[0]), "r"(a[1]), "r"(a[2]), "r"(a[3]), "r"(b0), "r"(b1));
}

__device__ __forceinline__ float fast_tanh(float x) {
    float ax = fabsf(x);
    float e = __expf(-2.0f * ax);
    float t = __fdividef(1.0f - e, 1.0f + e);
    return copysignf(t, x);
}
__device__ __forceinline__ float fast_sigmoid(float y) {
    return __fdividef(1.0f, 1.0f + __expf(-y));
}
__device__ __forceinline__ void split1(float v, __nv_bfloat16* hi, __nv_bfloat16* lo) {
    __nv_bfloat16 h = __float2bfloat16(v);
    *hi = h;
    *lo = __float2bfloat16(v - __bfloat162float(h));
}

// ---------------------------------------------------------------------------
// RMS norm + hi/lo split: one block per row of (BS, D)
// ---------------------------------------------------------------------------
__global__ void rms_kernel(const float* __restrict__ x, const float* __restrict__ w,
                           __nv_bfloat16* __restrict__ yhi,
                           __nv_bfloat16* __restrict__ ylo, int D) {
    size_t row = blockIdx.x;
    const float* xr = x + row * (size_t)D;
    __nv_bfloat16* yh = yhi + row * (size_t)D;
    __nv_bfloat16* yl = ylo + row * (size_t)D;

    float ss = 0.f;
    for (int d = threadIdx.x * 4; d < D; d += blockDim.x * 4) {
        float4 v = *(const float4*)&xr[d];
        ss += v.x * v.x + v.y * v.y + v.z * v.z + v.w * v.w;
    }
    #pragma unroll
    for (int o = 16; o > 0; o >>= 1) ss += __shfl_xor_sync(0xFFFFFFFFu, ss, o);
    __shared__ float sred[8];
    int wid = threadIdx.x >> 5, lane = threadIdx.x & 31;
    if (lane == 0) sred[wid] = ss;
    __syncthreads();
    if (wid == 0) {
        float t = (lane < (blockDim.x >> 5)) ? sred[lane] : 0.f;
        #pragma unroll
        for (int o = 4; o > 0; o >>= 1) t += __shfl_xor_sync(0xFFFFFFFFu, t, o);
        if (lane == 0) sred[0] = t;
    }
    __syncthreads();
    float inv = rsqrtf(sred[0] / (float)D + 1e-6f);

    for (int d = threadIdx.x * 4; d < D; d += blockDim.x * 4) {
        float4 v = *(const float4*)&xr[d];
        float4 wv = *(const float4*)&w[d];
        float r0 = wv.x * v.x * inv, r1 = wv.y * v.y * inv;
        float r2 = wv.z * v.z * inv, r3 = wv.w * v.w * inv;
        __nv_bfloat16 h[4], l[4];
        split1(r0, &h[0], &l[0]); split1(r1, &h[1], &l[1]);
        split1(r2, &h[2], &l[2]); split1(r3, &h[3], &l[3]);
        *(uint2*)&yh[d] = *(uint2*)h;
        *(uint2*)&yl[d] = *(uint2*)l;
    }
}

// ---------------------------------------------------------------------------
// Split 4 gate weights (P x D fp32 each) -> padded bf16 hi/lo slabs
// ---------------------------------------------------------------------------
__global__ void wsplit_kernel(const float* __restrict__ w0, const float* __restrict__ w1,
                              const float* __restrict__ w2, const float* __restrict__ w3,
                              __nv_bfloat16* __restrict__ whi,
                              __nv_bfloat16* __restrict__ wlo,
                              int P, int D) {
    size_t i4 = ((size_t)blockIdx.x * blockDim.x + threadIdx.x) * 4;
    size_t per = (size_t)P * D;
    if (i4 >= 4 * per) return;
    int z = (int)(i4 / per);
    size_t rem = i4 - (size_t)z * per;
    const float* W = (z == 0) ? w0 : (z == 1) ? w1 : (z == 2) ? w2 : w3;
    float4 v = *(const float4*)(W + rem);
    __nv_bfloat16 h[4], l[4];
    split1(v.x, &h[0], &l[0]); split1(v.y, &h[1], &l[1]);
    split1(v.z, &h[2], &l[2]); split1(v.w, &h[3], &l[3]);
    size_t dst = (size_t)z * MAX_PN * D + rem;
    *(uint2*)&whi[dst] = *(uint2*)h;
    *(uint2*)&wlo[dst] = *(uint2*)l;
}

// Pad+split Wout (D x P fp32) -> (D x Pp bf16 hi/lo), zero fill
__global__ void wosplit_kernel(const float* __restrict__ w,
                               __nv_bfloat16* __restrict__ whi,
                               __nv_bfloat16* __restrict__ wlo,
                               int D, int P, int Pp) {
    int i = blockIdx.x * blockDim.x + threadIdx.x;
    if (i >= D * Pp) return;
    int d = i / Pp, p = i - d * Pp;
    float v = (p < P) ? w[(size_t)d * P + p] : 0.f;
    __nv_bfloat16 h, l;
    split1(v, &h, &l);
    whi[i] = h;
    wlo[i] = l;
}

// ---------------------------------------------------------------------------
// GEMM: C[m,n] = sum_k A[m,k]*B[n,k]  (NT; pre-split bf16 hi/lo operands)
// CTA 128x128, 8 warps of 64x32, K-chunk 16, NSTAGE cp.async stages.
// Register software pipeline: Ahi/Bhi fragments for chunk t+1 are ldsm'd
// during chunk t (data already smem-resident); lo-tile ldsm issued at chunk
// top, consumed 16+ MMAs later. MMAs start each chunk with zero wait.
// ---------------------------------------------------------------------------
__device__ __forceinline__
void gemm_body(int m0, int n0,
               const __nv_bfloat16* __restrict__ Ah, const __nv_bfloat16* __restrict__ Al,
               int lda,
               const __nv_bfloat16* __restrict__ Bh, const __nv_bfloat16* __restrict__ Bl,
               int ldb,
               float* __restrict__ C, int ldc,
               const float* __restrict__ resid,
               int N, int K, int act)
{
    extern __shared__ __align__(16) char smem[];
    const uint32_t sb = smem_u32(smem);
    const int tid = threadIdx.x;
    const int lane = tid & 31;
    const int wid = tid >> 5;
    const int wm = wid >> 2;          // 0..1 -> 64 rows
    const int wn = wid & 3;           // 0..3 -> 32 cols

    const int NK = K / BKF;

    // fill mapping: 2 threads per row; each covers 8 bf16 (one 16B segment)
    const int frow = tid >> 1;
    const int fseg = (tid & 1) << 3;
    const __nv_bfloat16* ga  = Ah + (size_t)(m0 + frow) * lda + fseg;
    const __nv_bfloat16* gal = Al + (size_t)(m0 + frow) * lda + fseg;
    const __nv_bfloat16* gb  = Bh + (size_t)(n0 + frow) * ldb + fseg;
    const __nv_bfloat16* gbl = Bl + (size_t)(n0 + frow) * ldb + fseg;
    const uint32_t sd = sb + (uint32_t)(frow * PIT + fseg) * 2;

    float acc[4][4][4];
    #pragma unroll
    for (int a = 0; a < 4; a++)
        #pragma unroll
        for (int b = 0; b < 4; b++)
            #pragma unroll
            for (int c = 0; c < 4; c++) acc[a][b][c] = 0.f;

    // prologue: stages 0..NSTAGE-2 <- chunks 0..NSTAGE-2 (one commit each)
    #pragma unroll
    for (int s = 0; s < NSTAGE - 1; s++) {
        if (s < NK) {
            int ko = s * BKF;
            uint32_t ds = sd + s * STG;
            CP16(ds,           ga + ko);
            CP16(ds + HTB,     gal + ko);
            CP16(ds + 2 * HTB, gb + ko);
            CP16(ds + 3 * HTB, gbl + ko);
        }
        CPCOMMIT();
    }

    const int arow = wm * 64 + (lane & 15);
    const int brow = wn * 32 + (lane & 15);
    const int ksel = (lane >> 4) << 3;

    // persistent prefetched fragments (Ahi/Bhi of the *current* chunk)
    uint32_t ahfP[4][4], bhfP[2][4];

    // prologue prefetch: chunk 0 fragments
    CPWAIT(1);          // groups 0..2 committed -> chunks 0,1 done (thread)
    __syncthreads();    // CTA-wide visibility
    {
        const uint32_t ss = sb;  // stage 0
        #pragma unroll
        for (int mt = 0; mt < 4; mt++)
            ldsm4(ahfP[mt], ss + 2 * ((arow + mt * 16) * PIT + ksel));
        #pragma unroll
        for (int j = 0; j < 2; j++)
            ldsm4(bhfP[j], ss + 2 * HTB + 2 * ((brow + j * 16) * PIT + ksel));
    }

    for (int t = 0; t < NK; t++) {
        // invariant at top: chunks <= t+1 CTA-visible; barrier (loop bottom /
        // prologue) separates prior smem reads from this iter's overwrite.
        const uint32_t ss = sb + (uint32_t)(t % NSTAGE) * STG;
        uint32_t blf[2][4], alf[4][4];

        // issue lo-tile ldsm up front (consumed 16-32 MMAs later)
        #pragma unroll
        for (int j = 0; j < 2; j++)
            ldsm4(blf[j], ss + 3 * HTB + 2 * ((brow + j * 16) * PIT + ksel));
        #pragma unroll
        for (int mt = 0; mt < 4; mt++)
            ldsm4(alf[mt], ss + HTB + 2 * ((arow + mt * 16) * PIT + ksel));

        // hi*hi (fragments prefetched last iteration: zero wait)
        #pragma unroll
        for (int mt = 0; mt < 4; mt++)
            #pragma unroll
            for (int j = 0; j < 2; j++) {
                mma16816(acc[mt][2 * j],     ahfP[mt], bhfP[j][0], bhfP[j][2]);
                mma16816(acc[mt][2 * j + 1], ahfP[mt], bhfP[j][1], bhfP[j][3]);
            }
        // hi*lo
        #pragma unroll
        for (int mt = 0; mt < 4; mt++)
            #pragma unroll
            for (int j = 0; j < 2; j++) {
                mma16816(acc[mt][2 * j],     ahfP[mt], blf[j][0], blf[j][2]);
                mma16816(acc[mt][2 * j + 1], ahfP[mt], blf[j][1], blf[j][3]);
            }
        // lo*hi
        #pragma unroll
        for (int mt = 0; mt < 4; mt++)
            #pragma unroll
            for (int j = 0; j < 2; j++) {
                mma16816(acc[mt][2 * j],     alf[mt], bhfP[j][0], bhfP[j][2]);
                mma16816(acc[mt][2 * j + 1], alf[mt], bhfP[j][1], bhfP[j][3]);
            }

        // prefetch hi fragments of chunk t+1 (stage (t+1)%NSTAGE; visible)
        if (t + 1 < NK) {
            const uint32_t sn = sb + (uint32_t)((t + 1) % NSTAGE) * STG;
            #pragma unroll
            for (int mt = 0; mt < 4; mt++)
                ldsm4(ahfP[mt], sn + 2 * ((arow + mt * 16) * PIT + ksel));
            #pragma unroll
            for (int j = 0; j < 2; j++)
                ldsm4(bhfP[j], sn + 2 * HTB + 2 * ((brow + j * 16) * PIT + ksel));
        }

        // fill stage for chunk t+NSTAGE-1 (overwrites stage (t-1)%NSTAGE,
        // whose last readers ran in iter t-1; prior barrier separates).
        if (t + NSTAGE - 1 < NK) {
            int ko = (t + NSTAGE - 1) * BKF;
            uint32_t ds = sd + (uint32_t)((t + NSTAGE - 1) % NSTAGE) * STG;
            CP16(ds,           ga + ko);
            CP16(ds + HTB,     gal + ko);
            CP16(ds + 2 * HTB, gb + ko);
            CP16(ds + 3 * HTB, gbl + ko);
        }
        CPCOMMIT();         // empty group in tail keeps accounting aligned

        // establish top-of-loop invariant for iter t+1:
        // wait(1) -> chunks <= t+2 done (thread); bar -> CTA-visible, and
        // separates this iter's ldsm from next iter's stage overwrite.
        CPWAIT(1);
        __syncthreads();
    }

    // epilogue: frag c0..c3 = rows (r, r+8) x cols (c, c+1); streaming stores
    #pragma unroll
    for (int mt = 0; mt < 4; mt++) {
        int r0 = m0 + wm * 64 + mt * 16 + (lane >> 2);
        float* crow0 = C + (size_t)r0 * ldc;
        float* crow1 = C + (size_t)(r0 + 8) * ldc;
        const float* rrow0 = resid ? resid + (size_t)r0 * ldc : (const float*)0;
        const float* rrow1 = resid ? resid + (size_t)(r0 + 8) * ldc : (const float*)0;
        #pragma unroll
        for (int nt = 0; nt < 4; nt++) {
            int c = n0 + wn * 32 + nt * 8 + ((lane & 3) << 1);
            float v0 = acc[mt][nt][0], v1 = acc[mt][nt][1];
            float v2 = acc[mt][nt][2], v3 = acc[mt][nt][3];
            if (act) {
                v0 = fast_sigmoid(15.f * fast_tanh(v0 * (1.f / 15.f)));
                v1 = fast_sigmoid(15.f * fast_tanh(v1 * (1.f / 15.f)));
                v2 = fast_sigmoid(15.f * fast_tanh(v2 * (1.f / 15.f)));
                v3 = fast_sigmoid(15.f * fast_tanh(v3 * (1.f / 15.f)));
            }
            if (c + 1 < N) {
                if (rrow0) {
                    float2 ra = __ldcs((const float2*)&rrow0[c]);
                    float2 rb = __ldcs((const float2*)&rrow1[c]);
                    v0 += ra.x; v1 += ra.y;
                    v2 += rb.x; v3 += rb.y;
                }
                __stcs((float2*)&crow0[c], make_float2(v0, v1));
                __stcs((float2*)&crow1[c], make_float2(v2, v3));
            } else if (c < N) {
                if (rrow0) { v0 += __ldcs(&rrow0[c]); v2 += __ldcs(&rrow1[c]); }
                __stcs(&crow0[c], v0);
                __stcs(&crow1[c], v2);
            }
        }
    }
}

// Fused 4-gate GEMM. grid.x = n_tiles*4 with z = blockIdx.x & 3 (z fastest):
// CTAs sharing an (m,n) A tile are wave-co-resident -> A dedup in L2.
__global__ __launch_bounds__(256, 2)
void gemm_gates(const __nv_bfloat16* __restrict__ xh, const __nv_bfloat16* __restrict__ xl,
                int lda,
                const __nv_bfloat16* __restrict__ whi, const __nv_bfloat16* __restrict__ wlo,
                size_t wstride,
                float* __restrict__ gates, size_t gsz, int ldc,
                int N, int K)
{
    const int z = blockIdx.x & 3;
    const int n0 = (blockIdx.x >> 2) * BN;
    const int m0 = blockIdx.y * BM;
    gemm_body(m0, n0, xh, xl, lda,
              whi + (size_t)z * wstride, wlo + (size_t)z * wstride, lda,
              gates + (size_t)z * gsz, ldc, (const float*)0, N, K, z != 3);
}

// Output projection GEMM + residual.
__global__ __launch_bounds__(256, 2)
void gemm_out(const __nv_bfloat16* __restrict__ ah, const __nv_bfloat16* __restrict__ al,
              int lda,
              const __nv_bfloat16* __restrict__ bh, const __nv_bfloat16* __restrict__ bl,
              int ldb,
              float* __restrict__ C, int ldc,
              const float* __restrict__ resid, int N, int K)
{
    gemm_body(blockIdx.y * BM, blockIdx.x * BN,
              ah, al, lda, bh, bl, ldb, C, ldc, resid, N, K, 0);
}

// ---------------------------------------------------------------------------
// Chunked LSTM scan (3-pass affine composition); streaming loads throughout.
// ---------------------------------------------------------------------------
__global__ void scan_pass1(const float* __restrict__ gates,
                           float* __restrict__ Fout, float* __restrict__ Gout,
                           int B, int S, int P, int Pp, int CH) {
    int t = blockIdx.x * blockDim.x + threadIdx.x;
    int BP = B * P;
    if (t >= BP * NCHUNK) return;
    int idx = t % BP;
    int c = t / BP;
    int b = idx / P, p = idx - b * P;
    size_t GSZ = (size_t)B * S * Pp;
    size_t base = (size_t)b * S * Pp + p + (size_t)(c * CH) * Pp;
    const float* gi = gates + base;
    const float* gf = gates + GSZ + base;
    const float* gc = gates + 3 * GSZ + base;

    float F = 1.f, G = 0.f;
    #pragma unroll 4
    for (int s = 0; s < CH; s++) {
        size_t off = (size_t)s * Pp;
        float fv = __ldcs(gf + off);
        float iv = __ldcs(gi + off);
        float cv = __ldcs(gc + off);
        G = fv * G + iv * fast_tanh(cv);
        F *= fv;
    }
    Fout[t] = F;
    Gout[t] = G;
}

__global__ void scan_pass2(const float* __restrict__ F, const float* __restrict__ G,
                           const float* __restrict__ h0, float* __restrict__ hs,
                           float* __restrict__ hfin, int BP) {
    int idx = blockIdx.x * blockDim.x + threadIdx.x;
    if (idx >= BP) return;
    float h = h0[idx];
    #pragma unroll
    for (int c = 0; c < NCHUNK; c++) {
        hs[c * BP + idx] = h;
        h = __ldcs(F + c * BP + idx) * h + __ldcs(G + c * BP + idx);
    }
    hfin[idx] = h;
}

__global__ void scan_pass3(const float* __restrict__ gates,
                           const float* __restrict__ hs,
                           __nv_bfloat16* __restrict__ ohi,
                           __nv_bfloat16* __restrict__ olo,
                           int B, int S, int P, int Pp, int CH) {
    int t = blockIdx.x * blockDim.x + threadIdx.x;
    int BP = B * P;
    if (t >= BP * NCHUNK) return;
    int idx = t % BP;
    int c = t / BP;
    int b = idx / P, p = idx - b * P;
    size_t GSZ = (size_t)B * S * Pp;
    size_t base = (size_t)b * S * Pp + p + (size_t)(c * CH) * Pp;
    const float* gi = gates + base;
    const float* gf = gates + GSZ + base;
    const float* go = gates + 2 * GSZ + base;
    const float* gc = gates + 3 * GSZ + base;

    float h = hs[t];
    #pragma unroll 4
    for (int s = 0; s < CH; s++) {
        size_t off = (size_t)s * Pp;
        float fv = __ldcs(gf + off);
        float iv = __ldcs(gi + off);
        float ov = __ldcs(go + off);
        float cv = __ldcs(gc + off);
        h = fv * h + iv * fast_tanh(cv);
        float outv = ov * fast_tanh(h);
        __nv_bfloat16 hh, ll;
        split1(outv, &hh, &ll);
        ohi[base + off] = hh;
        olo[base + off] = ll;
    }
}

// Fallback fully-sequential scan (only if S % NCHUNK != 0).
__global__ void scan_seq(const float* __restrict__ gates,
                         __nv_bfloat16* __restrict__ ohi,
                         __nv_bfloat16* __restrict__ olo,
                         float* __restrict__ hfin, const float* __restrict__ h0,
                         int B, int S, int P, int Pp) {
    int idx = blockIdx.x * blockDim.x + threadIdx.x;
    if (idx >= B * P) return;
    int b = idx / P, p = idx - b * P;
    size_t GSZ = (size_t)B * S * Pp;
    size_t base = (size_t)b * S * Pp + p;
    const float* gi = gates + base;
    const float* gf = gates + GSZ + base;
    const float* go = gates + 2 * GSZ + base;
    const float* gc = gates + 3 * GSZ + base;
    float h = h0[idx];
    #pragma unroll 4
    for (int s = 0; s < S; s++) {
        size_t off = (size_t)s * Pp;
        float iv = __ldcs(gi + off);
        float fv = __ldcs(gf + off);
        float ov = __ldcs(go + off);
        float cv = __ldcs(gc + off);
        h = fv * h + iv * fast_tanh(cv);
        float outv = ov * fast_tanh(h);
        __nv_bfloat16 hh, ll;
        split1(outv, &hh, &ll);
        ohi[base + off] = hh;
        olo[base + off] = ll;
    }
    hfin[idx] = h;
}

// ---------------------------------------------------------------------------
// kernel_launch
// ---------------------------------------------------------------------------
extern "C" void kernel_launch(void* const* d_in, const int* in_sizes, int n_in,
                              void* d_out, int out_size) {
    (void)n_in;
    const float* x    = (const float*)d_in[0];
    const float* h0   = (const float*)d_in[1];
    const float* Wi   = (const float*)d_in[2];
    const float* Wf   = (const float*)d_in[3];
    const float* Wo   = (const float*)d_in[4];
    const float* Wc   = (const float*)d_in[5];
    const float* Wout = (const float*)d_in[6];
    const float* lnw  = (const float*)d_in[7];

    const int D  = in_sizes[7];              // 2048
    const int BS = in_sizes[0] / D;          // 8192
    const int P  = in_sizes[2] / D;          // 2729
    const int B  = in_sizes[1] / P;          // 4
    const int S  = BS / B;                   // 2048
    const int Pp = (P + 63) & ~63;           // 2752
    const int BP = B * P;

    float* out = (float*)d_out;

    __nv_bfloat16 *xnh, *xnl, *whi, *wlo, *woh, *wol, *ohi, *olo;
    float *gates, *Fbuf, *Gbuf, *hsbuf;
    cudaGetSymbolAddress((void**)&xnh, g_xnhi);
    cudaGetSymbolAddress((void**)&xnl, g_xnlo);
    cudaGetSymbolAddress((void**)&whi, g_whi);
    cudaGetSymbolAddress((void**)&wlo, g_wlo);
    cudaGetSymbolAddress((void**)&woh, g_wohi);
    cudaGetSymbolAddress((void**)&wol, g_wolo);
    cudaGetSymbolAddress((void**)&ohi, g_ohi);
    cudaGetSymbolAddress((void**)&olo, g_olo);
    cudaGetSymbolAddress((void**)&gates, g_gates);
    cudaGetSymbolAddress((void**)&Fbuf, g_F);
    cudaGetSymbolAddress((void**)&Gbuf, g_G);
    cudaGetSymbolAddress((void**)&hsbuf, g_hs);

    // h_final goes into d_out's tail only if out_size actually covers it.
    const size_t BSD = (size_t)BS * D;
    float* hfin = ((size_t)out_size >= BSD + (size_t)BP)
                      ? out + ((size_t)out_size - (size_t)BP)
                      : Fbuf;  // scratch; F fully consumed before hfin written

    cudaFuncSetAttribute(gemm_gates, cudaFuncAttributeMaxDynamicSharedMemorySize,
                         SMEMB);
    cudaFuncSetAttribute(gemm_out, cudaFuncAttributeMaxDynamicSharedMemorySize,
                         SMEMB);

    // 1) RMS norm (+ split)
    rms_kernel<<<BS, 256>>>(x, lnw, xnh, xnl, D);

    // 2) weight splits
    {
        size_t tot4 = 4ull * P * D / 4;
        wsplit_kernel<<<(unsigned)((tot4 + 255) / 256), 256>>>(Wi, Wf, Wo, Wc,
                                                               whi, wlo, P, D);
        int totw = D * Pp;
        wosplit_kernel<<<(totw + 255) / 256, 256>>>(Wout, woh, wol, D, P, Pp);
    }

    // 3) fused gate GEMMs (z folded into grid.x for L2 A dedup)
    {
        int ntiles = (P + BN - 1) / BN;
        dim3 gg(ntiles * 4, BS / BM, 1);
        size_t GSZ = (size_t)BS * Pp;
        gemm_gates<<<gg, 256, SMEMB>>>(xnh, xnl, D, whi, wlo,
                                       (size_t)MAX_PN * D,
                                       gates, GSZ, Pp, P, D);
    }

    // 4) LSTM scan
    if (S % NCHUNK == 0) {
        const int CH = S / NCHUNK;
        int tot = BP * NCHUNK;
        scan_pass1<<<(tot + 255) / 256, 256>>>(gates, Fbuf, Gbuf, B, S, P, Pp, CH);
        scan_pass2<<<(BP + 255) / 256, 256>>>(Fbuf, Gbuf, h0, hsbuf, hfin, BP);
        scan_pass3<<<(tot + 255) / 256, 256>>>(gates, hsbuf, ohi, olo,
                                               B, S, P, Pp, CH);
    } else {
        scan_seq<<<(BP + 255) / 256, 256>>>(gates, ohi, olo, hfin, h0, B, S, P, Pp);
    }

    // 5) output GEMM + residual
    dim3 gf((D + BN - 1) / BN, BS / BM);
    gemm_out<<<gf, 256, SMEMB>>>(ohi, olo, Pp, woh, wol, Pp, out, D, x, D, Pp);
}